// round 10
// baseline (speedup 1.0000x reference)
#include <cuda_runtime.h>
#include <cuda_bf16.h>
#include <cuda_fp16.h>

#define B_      64
#define C_      256
#define HW_     1024
#define NPIX    65536
#define NCODE   1024
#define CANDCAP 32
#define MARGIN  1e-3f

__device__ float g_a[NPIX];
__device__ float g_c[NCODE];
__device__ int   g_idx[NPIX];
__device__ float g_xT[(size_t)NPIX * C_];             // fp32 x, pixel-major
__device__ unsigned short g_xbf[(size_t)NPIX * C_];   // bf16 x, pixel-major
__device__ unsigned short g_wbf[NCODE * C_];          // bf16 codebook
__device__ short g_candj[(size_t)NPIX * CANDCAP];     // scratch (per-block)
__device__ float g_candh[(size_t)NPIX * CANDCAP];

// monotone float<->uint key for atomicMin on signed floats
__device__ __forceinline__ unsigned fkey(float f) {
    unsigned u = __float_as_uint(f);
    return (u & 0x80000000u) ? ~u : (u | 0x80000000u);
}
__device__ __forceinline__ float unfkey(unsigned k) {
    unsigned u = (k & 0x80000000u) ? (k & 0x7fffffffu) : ~k;
    return __uint_as_float(u);
}

__device__ __forceinline__ void ldm4(unsigned* r, unsigned addr) {
    asm volatile("ldmatrix.sync.aligned.m8n8.x4.shared.b16 {%0,%1,%2,%3}, [%4];"
                 : "=r"(r[0]), "=r"(r[1]), "=r"(r[2]), "=r"(r[3]) : "r"(addr));
}
__device__ __forceinline__ void mma16816(float* d, const unsigned* a,
                                         unsigned b0, unsigned b1) {
    asm volatile(
        "mma.sync.aligned.m16n8k16.row.col.f32.bf16.bf16.f32 "
        "{%0,%1,%2,%3}, {%4,%5,%6,%7}, {%8,%9}, {%0,%1,%2,%3};"
        : "+f"(d[0]), "+f"(d[1]), "+f"(d[2]), "+f"(d[3])
        : "r"(a[0]), "r"(a[1]), "r"(a[2]), "r"(a[3]), "r"(b0), "r"(b1));
}

// ---------------------------------------------------------------------------
// Fused prep + transpose:
//   side-work spread over blocks: codebook->bf16 (256 pairs/block via t<256)
//   and c_j = sum fl(w^2) sequential (2 rows/block via t in [256,258)).
//   main work: x (B,C,H,W)->(pix,k) fp32+bf16, a_p = sum fl(x^2) sequential.
// ---------------------------------------------------------------------------
__global__ void __launch_bounds__(512, 1)
t_kernel(const float* __restrict__ x, const float* __restrict__ w) {
    extern __shared__ float sm[];                    // [256][132]
    int t = threadIdx.x;
    int pixbase = blockIdx.x * 128;
    int b  = pixbase >> 10;
    int hw0 = pixbase & 1023;
    const float* xb = x + (size_t)b * C_ * HW_ + hw0;

    // ---- side-work: codebook bf16 conversion (512 blocks x 256 pairs) ----
    if (t < 256) {
        int i = blockIdx.x * 256 + t;                // < 131072 = NCODE*C_/2
        float2 v = reinterpret_cast<const float2*>(w)[i];
        __nv_bfloat162 b2 = __floats2bfloat162_rn(v.x, v.y);
        reinterpret_cast<unsigned*>(g_wbf)[i] = *reinterpret_cast<unsigned*>(&b2);
    } else if (t < 258) {
        // ---- side-work: c_j (2 rows/block), verbatim sequential arithmetic
        int j = blockIdx.x * 2 + (t - 256);          // < 1024
        const float* r = w + (size_t)j * C_;
        float s = 0.f;
        #pragma unroll 8
        for (int i = 0; i < C_; i++) s = __fadd_rn(s, __fmul_rn(r[i], r[i]));
        g_c[j] = s;
    }

    #pragma unroll 8
    for (int it = 0; it < 16; it++) {
        int idx = t + 512 * it;
        int c = idx >> 5, hq = idx & 31;
        float4 v = *reinterpret_cast<const float4*>(xb + (size_t)c * HW_ + 4 * hq);
        *reinterpret_cast<float4*>(&sm[c * 132 + 4 * hq]) = v;
    }
    __syncthreads();

    if (t < 128) {
        float s = 0.f;
        for (int k = 0; k < C_; k++) {
            float v = sm[k * 132 + t];
            s = __fadd_rn(s, __fmul_rn(v, v));
        }
        g_a[pixbase + t] = s;
    }

    #pragma unroll 4
    for (int it = 0; it < 16; it++) {
        int idx = t + 512 * it;
        int pl = idx >> 6, kq = idx & 63;
        float v0 = sm[(4 * kq + 0) * 132 + pl];
        float v1 = sm[(4 * kq + 1) * 132 + pl];
        float v2 = sm[(4 * kq + 2) * 132 + pl];
        float v3 = sm[(4 * kq + 3) * 132 + pl];
        size_t o = (size_t)(pixbase + pl) * C_ + 4 * kq;
        *reinterpret_cast<float4*>(g_xT + o) = make_float4(v0, v1, v2, v3);
        __nv_bfloat162 b01 = __floats2bfloat162_rn(v0, v1);
        __nv_bfloat162 b23 = __floats2bfloat162_rn(v2, v3);
        uint2 u = make_uint2(*reinterpret_cast<unsigned*>(&b01),
                             *reinterpret_cast<unsigned*>(&b23));
        *reinterpret_cast<uint2*>(g_xbf + o) = u;
    }
}

// ---------------------------------------------------------------------------
// bf16 MMA screen (hot loop VERBATIM from rounds 8/9, measured 137-141us x4)
// + fused in-kernel exact rescreen tail (each block sees all 1024 codes, so
// its end-of-loop min IS the final min). Overflow -> cooperative full scan.
// ---------------------------------------------------------------------------
__global__ void __launch_bounds__(256, 2)
g_kernel(const float* __restrict__ wt, float* __restrict__ out_idx,
         int write_idx) {
    extern __shared__ unsigned short smem_g[];
    unsigned short* xs = smem_g;               // [128][256] swizzled, 64KB
    unsigned short* ws = smem_g + 128 * 256;   // [64][256]  swizzled, 32KB
    __shared__ float    cs[NCODE];
    __shared__ unsigned minkey[128];
    __shared__ int      cnt_s[128];
    __shared__ float    sd2[256];
    __shared__ int      sj2[256];
    __shared__ int      ovf;

    int t = threadIdx.x, lane = t & 31, wid = t >> 5;
    int wm = wid >> 1, wn = wid & 1;
    int pixbase = blockIdx.x * 128;

    for (int i = t; i < NCODE; i += 256) cs[i] = g_c[i];
    if (t < 128) { minkey[t] = fkey(3.4e38f); cnt_s[t] = 0; }
    if (t == 0) ovf = 0;

    // load x tile (16B granules, XOR-swizzled by row&7)
    #pragma unroll 4
    for (int it = 0; it < 16; it++) {
        int flat = t + 256 * it;
        int pl = flat >> 5, gq = flat & 31;
        uint4 v = reinterpret_cast<const uint4*>(
            g_xbf + (size_t)(pixbase + pl) * C_)[gq];
        *reinterpret_cast<uint4*>(
            reinterpret_cast<char*>(xs) + pl * 512 + ((gq ^ (pl & 7)) * 16)) = v;
    }

    unsigned xs_u = (unsigned)__cvta_generic_to_shared(xs);
    unsigned ws_u = (unsigned)__cvta_generic_to_shared(ws);

    int asub = lane >> 3;
    int arow = (asub & 1) * 8 + (lane & 7);
    int acg  = asub >> 1;
    unsigned a_base[2];
    #pragma unroll
    for (int mt = 0; mt < 2; mt++)
        a_base[mt] = xs_u + (wm * 32 + mt * 16 + arow) * 512;
    int arx = arow & 7;

    int bcode = (lane & 7) + ((lane >> 4) & 1) * 8;
    int bkg   = (lane >> 3) & 1;
    unsigned b_base[2];
    #pragma unroll
    for (int n2 = 0; n2 < 2; n2++)
        b_base[n2] = ws_u + (wn * 32 + n2 * 16 + bcode) * 512;
    int brx = bcode & 7;

    int row_s[4];
    #pragma unroll
    for (int s = 0; s < 4; s++)
        row_s[s] = wm * 32 + (s >> 1) * 16 + (lane >> 2) + (s & 1) * 8;

    for (int cc = 0; cc < 16; cc++) {
        // ---- load w chunk (64 codes x 256 k) ----
        #pragma unroll
        for (int it = 0; it < 8; it++) {
            int flat = t + 256 * it;
            int cl = flat >> 5, gq = flat & 31;
            uint4 v = reinterpret_cast<const uint4*>(
                g_wbf + (size_t)(cc * 64 + cl) * C_)[gq];
            *reinterpret_cast<uint4*>(
                reinterpret_cast<char*>(ws) + cl * 512 + ((gq ^ (cl & 7)) * 16)) = v;
        }
        __syncthreads();

        float d[2][4][4];
        #pragma unroll
        for (int mt = 0; mt < 2; mt++)
            #pragma unroll
            for (int nt = 0; nt < 4; nt++)
                #pragma unroll
                for (int r = 0; r < 4; r++) d[mt][nt][r] = 0.f;

        #pragma unroll 4
        for (int ks = 0; ks < 16; ks++) {
            unsigned a[2][4], bf[2][4];
            #pragma unroll
            for (int mt = 0; mt < 2; mt++) {
                unsigned g = (unsigned)((2 * ks + acg) ^ arx);
                ldm4(a[mt], a_base[mt] + g * 16);
            }
            #pragma unroll
            for (int n2 = 0; n2 < 2; n2++) {
                unsigned g = (unsigned)((2 * ks + bkg) ^ brx);
                ldm4(bf[n2], b_base[n2] + g * 16);
            }
            #pragma unroll
            for (int mt = 0; mt < 2; mt++)
                #pragma unroll
                for (int nt = 0; nt < 4; nt++)
                    mma16816(d[mt][nt], a[mt],
                             bf[nt >> 1][(nt & 1) * 2], bf[nt >> 1][(nt & 1) * 2 + 1]);
        }

        // ---- h = fmaf(-2,dot,c) in place; per-row chunk min ----
        float rmin[4] = {3.4e38f, 3.4e38f, 3.4e38f, 3.4e38f};
        #pragma unroll
        for (int mt = 0; mt < 2; mt++)
            #pragma unroll
            for (int nt = 0; nt < 4; nt++)
                #pragma unroll
                for (int r = 0; r < 4; r++) {
                    int j = cc * 64 + wn * 32 + nt * 8 + 2 * (lane & 3) + (r & 1);
                    float h = fmaf(-2.f, d[mt][nt][r], cs[j]);
                    d[mt][nt][r] = h;
                    rmin[mt * 2 + (r >> 1)] = fminf(rmin[mt * 2 + (r >> 1)], h);
                }
        #pragma unroll
        for (int s = 0; s < 4; s++) {
            float m = rmin[s];
            m = fminf(m, __shfl_xor_sync(0xffffffffu, m, 1));
            m = fminf(m, __shfl_xor_sync(0xffffffffu, m, 2));
            if ((lane & 3) == 0) atomicMin(&minkey[row_s[s]], fkey(m));
        }
        __syncthreads();   // publish minkey; also: all mma reads of ws done

        // ---- append candidates (j, h) to gmem vs running prefix min ----
        float thr[4];
        #pragma unroll
        for (int s = 0; s < 4; s++) thr[s] = unfkey(minkey[row_s[s]]) + MARGIN;
        #pragma unroll
        for (int mt = 0; mt < 2; mt++)
            #pragma unroll
            for (int nt = 0; nt < 4; nt++)
                #pragma unroll
                for (int r = 0; r < 4; r++) {
                    int s = mt * 2 + (r >> 1);
                    float h = d[mt][nt][r];
                    if (h <= thr[s]) {
                        int p = row_s[s];
                        int j = cc * 64 + wn * 32 + nt * 8 + 2 * (lane & 3) + (r & 1);
                        int sl = atomicAdd(&cnt_s[p], 1);
                        if (sl < CANDCAP) {
                            size_t o = (size_t)(pixbase + p) * CANDCAP + sl;
                            g_candj[o] = (short)j;
                            g_candh[o] = h;
                        }
                    }
                }
        if (cc < 15) __syncthreads();
    }

    // ---- fused exact rescreen (verbatim round-1 arithmetic) ----
    __syncthreads();   // finalize minkey/cnt_s; block's gmem cand writes visible
    if (t < 128) {
        int pix = pixbase + t;
        int c = cnt_s[t];
        if (c <= CANDCAP) {
            float thr = unfkey(minkey[t]) + MARGIN;
            float a = g_a[pix];
            float bd = 3.4e38f;
            int   bj = 1 << 30;
            const float4* xr = reinterpret_cast<const float4*>(
                g_xT + (size_t)pix * C_);
            for (int s = 0; s < c; s++) {
                size_t o = (size_t)pix * CANDCAP + s;
                float h = g_candh[o];
                if (h > thr) continue;             // final-min filter
                int j = g_candj[o];
                const float4* wr = reinterpret_cast<const float4*>(
                    wt + (size_t)j * C_);
                float dot = 0.f;
                #pragma unroll 8
                for (int q = 0; q < 64; q++) {
                    float4 xv = xr[q], wv = wr[q];
                    dot = fmaf(xv.x, wv.x, dot);
                    dot = fmaf(xv.y, wv.y, dot);
                    dot = fmaf(xv.z, wv.z, dot);
                    dot = fmaf(xv.w, wv.w, dot);
                }
                float d2 = __fadd_rn(fmaf(-2.f, dot, a), cs[j]);
                if (d2 < bd || (d2 == bd && j < bj)) { bd = d2; bj = j; }
            }
            g_idx[pix] = bj;
            if (write_idx) out_idx[pix] = (float)bj;
        } else {
            ovf = 1;                               // benign race, same value
        }
    }
    __syncthreads();

    // ---- overflow safety net: cooperative exact full scan (~never) ----
    if (ovf) {
        for (int p = 0; p < 128; p++) {
            if (cnt_s[p] <= CANDCAP) continue;
            int pix = pixbase + p;
            float a = g_a[pix];
            const float4* xr = reinterpret_cast<const float4*>(
                g_xT + (size_t)pix * C_);
            float bd = 3.4e38f;
            int   bj = 1 << 30;
            for (int j = t; j < NCODE; j += 256) {
                const float4* wr = reinterpret_cast<const float4*>(
                    wt + (size_t)j * C_);
                float dot = 0.f;
                #pragma unroll 8
                for (int q = 0; q < 64; q++) {
                    float4 xv = xr[q], wv = wr[q];
                    dot = fmaf(xv.x, wv.x, dot);
                    dot = fmaf(xv.y, wv.y, dot);
                    dot = fmaf(xv.z, wv.z, dot);
                    dot = fmaf(xv.w, wv.w, dot);
                }
                float d2 = __fadd_rn(fmaf(-2.f, dot, a), cs[j]);
                if (d2 < bd || (d2 == bd && j < bj)) { bd = d2; bj = j; }
            }
            sd2[t] = bd; sj2[t] = bj;
            __syncthreads();
            for (int off = 128; off > 0; off >>= 1) {
                if (t < off) {
                    float dd = sd2[t + off]; int jj = sj2[t + off];
                    if (dd < sd2[t] || (dd == sd2[t] && jj < sj2[t])) {
                        sd2[t] = dd; sj2[t] = jj;
                    }
                }
                __syncthreads();
            }
            if (t == 0) {
                g_idx[pix] = sj2[0];
                if (write_idx) out_idx[pix] = (float)sj2[0];
            }
            __syncthreads();
        }
    }
}

// ---------------------------------------------------------------------------
// Scatter (round-9 verbatim): 512 threads, q = w[idx], ste = fl(fl(q-x)+x)
// ---------------------------------------------------------------------------
__global__ void __launch_bounds__(512, 1)
scatter_kernel(const float* __restrict__ x, const float* __restrict__ wt,
               float* __restrict__ out_q, float* __restrict__ out_ste,
               int has_ste) {
    extern __shared__ float sm[];          // [256][129]
    __shared__ int lidx[128];

    int t = threadIdx.x, lane = t & 31, warp = t >> 5;   // warp 0..15
    int pix_base = blockIdx.x * 128;
    int b  = pix_base >> 10;
    int hw = pix_base & 1023;

    if (t < 128) lidx[t] = g_idx[pix_base + t];
    __syncthreads();

    for (int rit = 0; rit < 8; rit++) {
        int r = warp + 16 * rit;
        const float* row = wt + (size_t)lidx[r] * C_;
        #pragma unroll
        for (int kit = 0; kit < 8; kit++) {
            int ci = lane + 32 * kit;
            sm[ci * 129 + r] = row[ci];
        }
    }
    __syncthreads();

    int hw_l = t & 127;
    int ch   = t >> 7;                     // 0..3
    for (int cit = 0; cit < 64; cit++) {
        int ci = ch + 4 * cit;
        size_t o = (size_t)b * C_ * HW_ + (size_t)ci * HW_ + hw + hw_l;
        float q = sm[ci * 129 + hw_l];
        out_q[o] = q;
        if (has_ste) {
            float xv = x[o];
            out_ste[o] = __fadd_rn(__fsub_rn(q, xv), xv);
        }
    }
}

// ---------------------------------------------------------------------------
extern "C" void kernel_launch(void* const* d_in, const int* in_sizes, int n_in,
                              void* d_out, int out_size) {
    const float* x  = (const float*)d_in[0];
    const float* wt = (const float*)d_in[1];
    float* out = (float*)d_out;

    const long long qsz = (long long)NPIX * C_;
    int has_ste = (out_size >= (int)(2 * qsz)) ? 1 : 0;
    int has_idx = (out_size >= (int)(2 * qsz) + NPIX) ||
                  (out_size == (int)qsz + NPIX);
    float* out_q   = out;
    float* out_ste = out + qsz;
    float* out_idx = has_ste ? out + 2 * qsz : out + qsz;

    cudaFuncSetAttribute(t_kernel,
        cudaFuncAttributeMaxDynamicSharedMemorySize, 256 * 132 * 4);
    cudaFuncSetAttribute(g_kernel,
        cudaFuncAttributeMaxDynamicSharedMemorySize, 98304);
    cudaFuncSetAttribute(scatter_kernel,
        cudaFuncAttributeMaxDynamicSharedMemorySize, 132096);

    t_kernel<<<NPIX / 128, 512, 256 * 132 * 4>>>(x, wt);
    g_kernel<<<NPIX / 128, 256, 98304>>>(wt, out_idx, has_idx ? 1 : 0);
    scatter_kernel<<<NPIX / 128, 512, 132096>>>(x, wt, out_q, out_ste, has_ste);
}

// round 11
// speedup vs baseline: 1.0525x; 1.0525x over previous
#include <cuda_runtime.h>
#include <cuda_bf16.h>
#include <cuda_fp16.h>

#define B_      64
#define C_      256
#define HW_     1024
#define NPIX    65536
#define NCODE   1024
#define CANDCAP 32
#define MARGIN  1e-3f

__device__ float g_a[NPIX];
__device__ float g_c[NCODE];
__device__ int   g_idx[NPIX];
__device__ float g_xT[(size_t)NPIX * C_];             // fp32 x, pixel-major
__device__ unsigned short g_xbf[(size_t)NPIX * C_];   // bf16 x, pixel-major
__device__ unsigned short g_wbf[NCODE * C_];          // bf16 codebook
__device__ short g_candj[(size_t)NPIX * CANDCAP];
__device__ float g_candh[(size_t)NPIX * CANDCAP];
__device__ float g_minh[NPIX];                        // final_min + MARGIN
__device__ int   g_ccnt[NPIX];

// monotone float<->uint key for atomicMin on signed floats
__device__ __forceinline__ unsigned fkey(float f) {
    unsigned u = __float_as_uint(f);
    return (u & 0x80000000u) ? ~u : (u | 0x80000000u);
}
__device__ __forceinline__ float unfkey(unsigned k) {
    unsigned u = (k & 0x80000000u) ? (k & 0x7fffffffu) : ~k;
    return __uint_as_float(u);
}

__device__ __forceinline__ void ldm4(unsigned* r, unsigned addr) {
    asm volatile("ldmatrix.sync.aligned.m8n8.x4.shared.b16 {%0,%1,%2,%3}, [%4];"
                 : "=r"(r[0]), "=r"(r[1]), "=r"(r[2]), "=r"(r[3]) : "r"(addr));
}
__device__ __forceinline__ void mma16816(float* d, const unsigned* a,
                                         unsigned b0, unsigned b1) {
    asm volatile(
        "mma.sync.aligned.m16n8k16.row.col.f32.bf16.bf16.f32 "
        "{%0,%1,%2,%3}, {%4,%5,%6,%7}, {%8,%9}, {%0,%1,%2,%3};"
        : "+f"(d[0]), "+f"(d[1]), "+f"(d[2]), "+f"(d[3])
        : "r"(a[0]), "r"(a[1]), "r"(a[2]), "r"(a[3]), "r"(b0), "r"(b1));
}

// ---------------------------------------------------------------------------
// c_j = sum fl(w^2) sequential (exact, matches reference rounding model)
// ---------------------------------------------------------------------------
__global__ void c_kernel(const float* __restrict__ w) {
    int j = blockIdx.x * blockDim.x + threadIdx.x;
    if (j < NCODE) {
        const float* r = w + (size_t)j * C_;
        float s = 0.f;
        #pragma unroll 8
        for (int i = 0; i < C_; i++) s = __fadd_rn(s, __fmul_rn(r[i], r[i]));
        g_c[j] = s;
    }
}

// ---------------------------------------------------------------------------
// codebook -> bf16
// ---------------------------------------------------------------------------
__global__ void wcvt_kernel(const float* __restrict__ w) {
    int i = blockIdx.x * blockDim.x + threadIdx.x;   // over pairs
    if (i < NCODE * C_ / 2) {
        float2 v = reinterpret_cast<const float2*>(w)[i];
        __nv_bfloat162 b2 = __floats2bfloat162_rn(v.x, v.y);
        reinterpret_cast<unsigned*>(g_wbf)[i] = *reinterpret_cast<unsigned*>(&b2);
    }
}

// ---------------------------------------------------------------------------
// Transpose x (B,C,H,W)->(pix,k) fp32 + bf16, and a_p = sum fl(x^2) seq.
// 64-pixel tiles, [256][68] smem (68KB) -> 3 blocks/SM, 1024 blocks.
// Arithmetic and value flow identical to the proven version.
// ---------------------------------------------------------------------------
#define TP 68
__global__ void __launch_bounds__(256, 3)
t_kernel(const float* __restrict__ x) {
    extern __shared__ float sm[];                    // [256][TP]
    int t = threadIdx.x;
    int pixbase = blockIdx.x * 64;
    int b  = pixbase >> 10;
    int hw0 = pixbase & 1023;
    const float* xb = x + (size_t)b * C_ * HW_ + hw0;

    // load: 256 ch x 64 hw (16 float4 per row, 16 threads/row -> coalesced)
    #pragma unroll 8
    for (int it = 0; it < 16; it++) {
        int idx = t + 256 * it;
        int c = idx >> 4, hq = idx & 15;
        float4 v = *reinterpret_cast<const float4*>(xb + (size_t)c * HW_ + 4 * hq);
        *reinterpret_cast<float4*>(&sm[c * TP + 4 * hq]) = v;
    }
    __syncthreads();

    if (t < 64) {
        float s = 0.f;
        for (int k = 0; k < C_; k++) {
            float v = sm[k * TP + t];
            s = __fadd_rn(s, __fmul_rn(v, v));
        }
        g_a[pixbase + t] = s;
    }

    // write: 64 pixels x 256 k (warp covers 512B contiguous per pixel row)
    #pragma unroll 4
    for (int it = 0; it < 16; it++) {
        int idx = t + 256 * it;
        int pl = idx >> 6, kq = idx & 63;
        float v0 = sm[(4 * kq + 0) * TP + pl];
        float v1 = sm[(4 * kq + 1) * TP + pl];
        float v2 = sm[(4 * kq + 2) * TP + pl];
        float v3 = sm[(4 * kq + 3) * TP + pl];
        size_t o = (size_t)(pixbase + pl) * C_ + 4 * kq;
        *reinterpret_cast<float4*>(g_xT + o) = make_float4(v0, v1, v2, v3);
        __nv_bfloat162 b01 = __floats2bfloat162_rn(v0, v1);
        __nv_bfloat162 b23 = __floats2bfloat162_rn(v2, v3);
        uint2 u = make_uint2(*reinterpret_cast<unsigned*>(&b01),
                             *reinterpret_cast<unsigned*>(&b23));
        *reinterpret_cast<uint2*>(g_xbf + o) = u;
    }
}

// ---------------------------------------------------------------------------
// bf16 MMA screen (rounds 8/9 VERBATIM, measured 137-141us x4).
// Online candidate collection into GMEM (j, h pairs) + final threshold.
// ---------------------------------------------------------------------------
__global__ void __launch_bounds__(256, 2)
g_kernel() {
    extern __shared__ unsigned short smem_g[];
    unsigned short* xs = smem_g;               // [128][256] swizzled, 64KB
    unsigned short* ws = smem_g + 128 * 256;   // [64][256]  swizzled, 32KB
    __shared__ float    cs[NCODE];
    __shared__ unsigned minkey[128];
    __shared__ int      cnt_s[128];

    int t = threadIdx.x, lane = t & 31, wid = t >> 5;
    int wm = wid >> 1, wn = wid & 1;
    int pixbase = blockIdx.x * 128;

    for (int i = t; i < NCODE; i += 256) cs[i] = g_c[i];
    if (t < 128) { minkey[t] = fkey(3.4e38f); cnt_s[t] = 0; }

    // load x tile (16B granules, XOR-swizzled by row&7)
    #pragma unroll 4
    for (int it = 0; it < 16; it++) {
        int flat = t + 256 * it;
        int pl = flat >> 5, gq = flat & 31;
        uint4 v = reinterpret_cast<const uint4*>(
            g_xbf + (size_t)(pixbase + pl) * C_)[gq];
        *reinterpret_cast<uint4*>(
            reinterpret_cast<char*>(xs) + pl * 512 + ((gq ^ (pl & 7)) * 16)) = v;
    }

    unsigned xs_u = (unsigned)__cvta_generic_to_shared(xs);
    unsigned ws_u = (unsigned)__cvta_generic_to_shared(ws);

    int asub = lane >> 3;
    int arow = (asub & 1) * 8 + (lane & 7);
    int acg  = asub >> 1;
    unsigned a_base[2];
    #pragma unroll
    for (int mt = 0; mt < 2; mt++)
        a_base[mt] = xs_u + (wm * 32 + mt * 16 + arow) * 512;
    int arx = arow & 7;

    int bcode = (lane & 7) + ((lane >> 4) & 1) * 8;
    int bkg   = (lane >> 3) & 1;
    unsigned b_base[2];
    #pragma unroll
    for (int n2 = 0; n2 < 2; n2++)
        b_base[n2] = ws_u + (wn * 32 + n2 * 16 + bcode) * 512;
    int brx = bcode & 7;

    int row_s[4];
    #pragma unroll
    for (int s = 0; s < 4; s++)
        row_s[s] = wm * 32 + (s >> 1) * 16 + (lane >> 2) + (s & 1) * 8;

    for (int cc = 0; cc < 16; cc++) {
        // ---- load w chunk (64 codes x 256 k) ----
        #pragma unroll
        for (int it = 0; it < 8; it++) {
            int flat = t + 256 * it;
            int cl = flat >> 5, gq = flat & 31;
            uint4 v = reinterpret_cast<const uint4*>(
                g_wbf + (size_t)(cc * 64 + cl) * C_)[gq];
            *reinterpret_cast<uint4*>(
                reinterpret_cast<char*>(ws) + cl * 512 + ((gq ^ (cl & 7)) * 16)) = v;
        }
        __syncthreads();

        float d[2][4][4];
        #pragma unroll
        for (int mt = 0; mt < 2; mt++)
            #pragma unroll
            for (int nt = 0; nt < 4; nt++)
                #pragma unroll
                for (int r = 0; r < 4; r++) d[mt][nt][r] = 0.f;

        #pragma unroll 4
        for (int ks = 0; ks < 16; ks++) {
            unsigned a[2][4], bf[2][4];
            #pragma unroll
            for (int mt = 0; mt < 2; mt++) {
                unsigned g = (unsigned)((2 * ks + acg) ^ arx);
                ldm4(a[mt], a_base[mt] + g * 16);
            }
            #pragma unroll
            for (int n2 = 0; n2 < 2; n2++) {
                unsigned g = (unsigned)((2 * ks + bkg) ^ brx);
                ldm4(bf[n2], b_base[n2] + g * 16);
            }
            #pragma unroll
            for (int mt = 0; mt < 2; mt++)
                #pragma unroll
                for (int nt = 0; nt < 4; nt++)
                    mma16816(d[mt][nt], a[mt],
                             bf[nt >> 1][(nt & 1) * 2], bf[nt >> 1][(nt & 1) * 2 + 1]);
        }

        // ---- h = fmaf(-2,dot,c) in place; per-row chunk min ----
        float rmin[4] = {3.4e38f, 3.4e38f, 3.4e38f, 3.4e38f};
        #pragma unroll
        for (int mt = 0; mt < 2; mt++)
            #pragma unroll
            for (int nt = 0; nt < 4; nt++)
                #pragma unroll
                for (int r = 0; r < 4; r++) {
                    int j = cc * 64 + wn * 32 + nt * 8 + 2 * (lane & 3) + (r & 1);
                    float h = fmaf(-2.f, d[mt][nt][r], cs[j]);
                    d[mt][nt][r] = h;
                    rmin[mt * 2 + (r >> 1)] = fminf(rmin[mt * 2 + (r >> 1)], h);
                }
        #pragma unroll
        for (int s = 0; s < 4; s++) {
            float m = rmin[s];
            m = fminf(m, __shfl_xor_sync(0xffffffffu, m, 1));
            m = fminf(m, __shfl_xor_sync(0xffffffffu, m, 2));
            if ((lane & 3) == 0) atomicMin(&minkey[row_s[s]], fkey(m));
        }
        __syncthreads();   // publish minkey; also: all mma reads of ws done

        // ---- append candidates (j, h) to gmem vs running prefix min ----
        float thr[4];
        #pragma unroll
        for (int s = 0; s < 4; s++) thr[s] = unfkey(minkey[row_s[s]]) + MARGIN;
        #pragma unroll
        for (int mt = 0; mt < 2; mt++)
            #pragma unroll
            for (int nt = 0; nt < 4; nt++)
                #pragma unroll
                for (int r = 0; r < 4; r++) {
                    int s = mt * 2 + (r >> 1);
                    float h = d[mt][nt][r];
                    if (h <= thr[s]) {
                        int p = row_s[s];
                        int j = cc * 64 + wn * 32 + nt * 8 + 2 * (lane & 3) + (r & 1);
                        int sl = atomicAdd(&cnt_s[p], 1);
                        if (sl < CANDCAP) {
                            size_t o = (size_t)(pixbase + p) * CANDCAP + sl;
                            g_candj[o] = (short)j;
                            g_candh[o] = h;
                        }
                    }
                }
        if (cc < 15) __syncthreads();
    }

    // ---- emit counts + final threshold ----
    __syncthreads();
    if (t < 128) {
        int pix = pixbase + t;
        int c = cnt_s[t];
        g_ccnt[pix] = (c > CANDCAP) ? NCODE : c;
        g_minh[pix] = unfkey(minkey[t]) + MARGIN;
    }
}

// ---------------------------------------------------------------------------
// Exact rescreen (round-8/9 verbatim): filter vs final threshold, then
// sequential-k fp32 fmaf dot, d2 = fl(fmaf(-2,dot,a)+c), lexicographic (d2,j).
// ---------------------------------------------------------------------------
__global__ void __launch_bounds__(256, 4)
s2_kernel(const float* __restrict__ wt, float* __restrict__ out_idx,
          int write_idx) {
    __shared__ float sd[256];
    __shared__ int   sj[256];
    int t = threadIdx.x;
    int pix = blockIdx.x * 32 + (t >> 3);
    int sl = t & 7;

    int cnt = g_ccnt[pix];
    const float4* xr = reinterpret_cast<const float4*>(g_xT + (size_t)pix * C_);
    float a = g_a[pix];
    float bd = 3.4e38f;
    int   bj = 1 << 30;

    if (cnt <= CANDCAP) {
        float thr = g_minh[pix];
        for (int s = sl; s < cnt; s += 8) {
            size_t o = (size_t)pix * CANDCAP + s;
            float h = g_candh[o];
            if (h > thr) continue;                 // final-min filter
            int j = g_candj[o];
            const float4* wr = reinterpret_cast<const float4*>(wt + (size_t)j * C_);
            float dot = 0.f;
            #pragma unroll 8
            for (int q = 0; q < 64; q++) {
                float4 xv = xr[q], wv = wr[q];
                dot = fmaf(xv.x, wv.x, dot);
                dot = fmaf(xv.y, wv.y, dot);
                dot = fmaf(xv.z, wv.z, dot);
                dot = fmaf(xv.w, wv.w, dot);
            }
            float d2 = __fadd_rn(fmaf(-2.f, dot, a), g_c[j]);
            if (d2 < bd || (d2 == bd && j < bj)) { bd = d2; bj = j; }
        }
    } else {  // safety net: exact full scan (raw overflow, ~never)
        for (int j = sl; j < NCODE; j += 8) {
            const float4* wr = reinterpret_cast<const float4*>(wt + (size_t)j * C_);
            float dot = 0.f;
            #pragma unroll 8
            for (int q = 0; q < 64; q++) {
                float4 xv = xr[q], wv = wr[q];
                dot = fmaf(xv.x, wv.x, dot);
                dot = fmaf(xv.y, wv.y, dot);
                dot = fmaf(xv.z, wv.z, dot);
                dot = fmaf(xv.w, wv.w, dot);
            }
            float d2 = __fadd_rn(fmaf(-2.f, dot, a), g_c[j]);
            if (d2 < bd || (d2 == bd && j < bj)) { bd = d2; bj = j; }
        }
    }
    sd[t] = bd; sj[t] = bj;
    __syncthreads();
    if (sl == 0) {
        #pragma unroll
        for (int k = 1; k < 8; k++) {
            float d = sd[t + k]; int j = sj[t + k];
            if (d < bd || (d == bd && j < bj)) { bd = d; bj = j; }
        }
        g_idx[pix] = bj;
        if (write_idx) out_idx[pix] = (float)bj;
    }
}

// ---------------------------------------------------------------------------
// Scatter (round-9 verbatim): 512 threads, q = w[idx], ste = fl(fl(q-x)+x)
// ---------------------------------------------------------------------------
__global__ void __launch_bounds__(512, 1)
scatter_kernel(const float* __restrict__ x, const float* __restrict__ wt,
               float* __restrict__ out_q, float* __restrict__ out_ste,
               int has_ste) {
    extern __shared__ float sm[];          // [256][129]
    __shared__ int lidx[128];

    int t = threadIdx.x, lane = t & 31, warp = t >> 5;   // warp 0..15
    int pix_base = blockIdx.x * 128;
    int b  = pix_base >> 10;
    int hw = pix_base & 1023;

    if (t < 128) lidx[t] = g_idx[pix_base + t];
    __syncthreads();

    for (int rit = 0; rit < 8; rit++) {
        int r = warp + 16 * rit;
        const float* row = wt + (size_t)lidx[r] * C_;
        #pragma unroll
        for (int kit = 0; kit < 8; kit++) {
            int ci = lane + 32 * kit;
            sm[ci * 129 + r] = row[ci];
        }
    }
    __syncthreads();

    int hw_l = t & 127;
    int ch   = t >> 7;                     // 0..3
    for (int cit = 0; cit < 64; cit++) {
        int ci = ch + 4 * cit;
        size_t o = (size_t)b * C_ * HW_ + (size_t)ci * HW_ + hw + hw_l;
        float q = sm[ci * 129 + hw_l];
        out_q[o] = q;
        if (has_ste) {
            float xv = x[o];
            out_ste[o] = __fadd_rn(__fsub_rn(q, xv), xv);
        }
    }
}

// ---------------------------------------------------------------------------
extern "C" void kernel_launch(void* const* d_in, const int* in_sizes, int n_in,
                              void* d_out, int out_size) {
    const float* x  = (const float*)d_in[0];
    const float* wt = (const float*)d_in[1];
    float* out = (float*)d_out;

    const long long qsz = (long long)NPIX * C_;
    int has_ste = (out_size >= (int)(2 * qsz)) ? 1 : 0;
    int has_idx = (out_size >= (int)(2 * qsz) + NPIX) ||
                  (out_size == (int)qsz + NPIX);
    float* out_q   = out;
    float* out_ste = out + qsz;
    float* out_idx = has_ste ? out + 2 * qsz : out + qsz;

    cudaFuncSetAttribute(t_kernel,
        cudaFuncAttributeMaxDynamicSharedMemorySize, 256 * TP * 4);
    cudaFuncSetAttribute(g_kernel,
        cudaFuncAttributeMaxDynamicSharedMemorySize, 98304);
    cudaFuncSetAttribute(scatter_kernel,
        cudaFuncAttributeMaxDynamicSharedMemorySize, 132096);

    c_kernel<<<4, 256>>>(wt);
    wcvt_kernel<<<NCODE * C_ / 2 / 256, 256>>>(wt);
    t_kernel<<<NPIX / 64, 256, 256 * TP * 4>>>(x);
    g_kernel<<<NPIX / 128, 256, 98304>>>();
    s2_kernel<<<NPIX / 32, 256>>>(wt, out_idx, has_idx ? 1 : 0);
    scatter_kernel<<<NPIX / 128, 512, 132096>>>(x, wt, out_q, out_ste, has_ste);
}

// round 12
// speedup vs baseline: 1.3674x; 1.2992x over previous
#include <cuda_runtime.h>
#include <cuda_bf16.h>
#include <cuda_fp16.h>

#define B_      64
#define C_      256
#define HW_     1024
#define NPIX    65536
#define NCODE   1024
#define CANDCAP 32
#define MARGIN  1e-3f

__device__ float g_a[NPIX];
__device__ float g_c[NCODE];
__device__ int   g_idx[NPIX];
__device__ float g_xT[(size_t)NPIX * C_];             // fp32 x, pixel-major
__device__ unsigned short g_xbf[(size_t)NPIX * C_];   // bf16 x, pixel-major
__device__ unsigned short g_wbf[NCODE * C_];          // bf16 codebook
__device__ short g_candj[(size_t)NPIX * CANDCAP];
__device__ float g_candh[(size_t)NPIX * CANDCAP];
__device__ float g_minh[NPIX];                        // final_min + MARGIN
__device__ int   g_ccnt[NPIX];

// monotone float<->uint key for atomicMin on signed floats
__device__ __forceinline__ unsigned fkey(float f) {
    unsigned u = __float_as_uint(f);
    return (u & 0x80000000u) ? ~u : (u | 0x80000000u);
}
__device__ __forceinline__ float unfkey(unsigned k) {
    unsigned u = (k & 0x80000000u) ? (k & 0x7fffffffu) : ~k;
    return __uint_as_float(u);
}

__device__ __forceinline__ void ldm4(unsigned* r, unsigned addr) {
    asm volatile("ldmatrix.sync.aligned.m8n8.x4.shared.b16 {%0,%1,%2,%3}, [%4];"
                 : "=r"(r[0]), "=r"(r[1]), "=r"(r[2]), "=r"(r[3]) : "r"(addr));
}
__device__ __forceinline__ void mma16816(float* d, const unsigned* a,
                                         unsigned b0, unsigned b1) {
    asm volatile(
        "mma.sync.aligned.m16n8k16.row.col.f32.bf16.bf16.f32 "
        "{%0,%1,%2,%3}, {%4,%5,%6,%7}, {%8,%9}, {%0,%1,%2,%3};"
        : "+f"(d[0]), "+f"(d[1]), "+f"(d[2]), "+f"(d[3])
        : "r"(a[0]), "r"(a[1]), "r"(a[2]), "r"(a[3]), "r"(b0), "r"(b1));
}

// ---------------------------------------------------------------------------
// c_j = sum fl(w^2) sequential (exact, matches reference rounding model)
// ---------------------------------------------------------------------------
__global__ void c_kernel(const float* __restrict__ w) {
    int j = blockIdx.x * blockDim.x + threadIdx.x;
    if (j < NCODE) {
        const float* r = w + (size_t)j * C_;
        float s = 0.f;
        #pragma unroll 8
        for (int i = 0; i < C_; i++) s = __fadd_rn(s, __fmul_rn(r[i], r[i]));
        g_c[j] = s;
    }
}

// ---------------------------------------------------------------------------
// codebook -> bf16
// ---------------------------------------------------------------------------
__global__ void wcvt_kernel(const float* __restrict__ w) {
    int i = blockIdx.x * blockDim.x + threadIdx.x;   // over pairs
    if (i < NCODE * C_ / 2) {
        float2 v = reinterpret_cast<const float2*>(w)[i];
        __nv_bfloat162 b2 = __floats2bfloat162_rn(v.x, v.y);
        reinterpret_cast<unsigned*>(g_wbf)[i] = *reinterpret_cast<unsigned*>(&b2);
    }
}

// ---------------------------------------------------------------------------
// t_bf: x (B,C,H,W) -> bf16 pixel-major g_xbf (g's only x dependency).
// Round-9 proven 512-thread / [256][132] structure, bf16 path verbatim.
// ---------------------------------------------------------------------------
__global__ void __launch_bounds__(512, 1)
t_bf_kernel(const float* __restrict__ x) {
    extern __shared__ float sm[];                    // [256][132]
    int t = threadIdx.x;
    int pixbase = blockIdx.x * 128;
    int b  = pixbase >> 10;
    int hw0 = pixbase & 1023;
    const float* xb = x + (size_t)b * C_ * HW_ + hw0;

    #pragma unroll 8
    for (int it = 0; it < 16; it++) {
        int idx = t + 512 * it;
        int c = idx >> 5, hq = idx & 31;
        float4 v = *reinterpret_cast<const float4*>(xb + (size_t)c * HW_ + 4 * hq);
        *reinterpret_cast<float4*>(&sm[c * 132 + 4 * hq]) = v;
    }
    __syncthreads();

    #pragma unroll 4
    for (int it = 0; it < 16; it++) {
        int idx = t + 512 * it;
        int pl = idx >> 6, kq = idx & 63;
        float v0 = sm[(4 * kq + 0) * 132 + pl];
        float v1 = sm[(4 * kq + 1) * 132 + pl];
        float v2 = sm[(4 * kq + 2) * 132 + pl];
        float v3 = sm[(4 * kq + 3) * 132 + pl];
        size_t o = (size_t)(pixbase + pl) * C_ + 4 * kq;
        __nv_bfloat162 b01 = __floats2bfloat162_rn(v0, v1);
        __nv_bfloat162 b23 = __floats2bfloat162_rn(v2, v3);
        uint2 u = make_uint2(*reinterpret_cast<unsigned*>(&b01),
                             *reinterpret_cast<unsigned*>(&b23));
        *reinterpret_cast<uint2*>(g_xbf + o) = u;
    }
}

// ---------------------------------------------------------------------------
// t_fp: x -> fp32 pixel-major g_xT + a_p = sum fl(x^2) sequential.
// Runs on a SIDE graph branch concurrent with t_bf/g (s2 deps only).
// Arithmetic verbatim round-9.
// ---------------------------------------------------------------------------
__global__ void __launch_bounds__(512, 1)
t_fp_kernel(const float* __restrict__ x) {
    extern __shared__ float sm[];                    // [256][132]
    int t = threadIdx.x;
    int pixbase = blockIdx.x * 128;
    int b  = pixbase >> 10;
    int hw0 = pixbase & 1023;
    const float* xb = x + (size_t)b * C_ * HW_ + hw0;

    #pragma unroll 8
    for (int it = 0; it < 16; it++) {
        int idx = t + 512 * it;
        int c = idx >> 5, hq = idx & 31;
        float4 v = *reinterpret_cast<const float4*>(xb + (size_t)c * HW_ + 4 * hq);
        *reinterpret_cast<float4*>(&sm[c * 132 + 4 * hq]) = v;
    }
    __syncthreads();

    if (t < 128) {
        float s = 0.f;
        for (int k = 0; k < C_; k++) {
            float v = sm[k * 132 + t];
            s = __fadd_rn(s, __fmul_rn(v, v));
        }
        g_a[pixbase + t] = s;
    }

    #pragma unroll 4
    for (int it = 0; it < 16; it++) {
        int idx = t + 512 * it;
        int pl = idx >> 6, kq = idx & 63;
        float v0 = sm[(4 * kq + 0) * 132 + pl];
        float v1 = sm[(4 * kq + 1) * 132 + pl];
        float v2 = sm[(4 * kq + 2) * 132 + pl];
        float v3 = sm[(4 * kq + 3) * 132 + pl];
        size_t o = (size_t)(pixbase + pl) * C_ + 4 * kq;
        *reinterpret_cast<float4*>(g_xT + o) = make_float4(v0, v1, v2, v3);
    }
}

// ---------------------------------------------------------------------------
// bf16 MMA screen (rounds 8/9 VERBATIM). Online candidate collection into
// GMEM (j, h pairs) + final threshold.
// ---------------------------------------------------------------------------
__global__ void __launch_bounds__(256, 2)
g_kernel() {
    extern __shared__ unsigned short smem_g[];
    unsigned short* xs = smem_g;               // [128][256] swizzled, 64KB
    unsigned short* ws = smem_g + 128 * 256;   // [64][256]  swizzled, 32KB
    __shared__ float    cs[NCODE];
    __shared__ unsigned minkey[128];
    __shared__ int      cnt_s[128];

    int t = threadIdx.x, lane = t & 31, wid = t >> 5;
    int wm = wid >> 1, wn = wid & 1;
    int pixbase = blockIdx.x * 128;

    for (int i = t; i < NCODE; i += 256) cs[i] = g_c[i];
    if (t < 128) { minkey[t] = fkey(3.4e38f); cnt_s[t] = 0; }

    // load x tile (16B granules, XOR-swizzled by row&7)
    #pragma unroll 4
    for (int it = 0; it < 16; it++) {
        int flat = t + 256 * it;
        int pl = flat >> 5, gq = flat & 31;
        uint4 v = reinterpret_cast<const uint4*>(
            g_xbf + (size_t)(pixbase + pl) * C_)[gq];
        *reinterpret_cast<uint4*>(
            reinterpret_cast<char*>(xs) + pl * 512 + ((gq ^ (pl & 7)) * 16)) = v;
    }

    unsigned xs_u = (unsigned)__cvta_generic_to_shared(xs);
    unsigned ws_u = (unsigned)__cvta_generic_to_shared(ws);

    int asub = lane >> 3;
    int arow = (asub & 1) * 8 + (lane & 7);
    int acg  = asub >> 1;
    unsigned a_base[2];
    #pragma unroll
    for (int mt = 0; mt < 2; mt++)
        a_base[mt] = xs_u + (wm * 32 + mt * 16 + arow) * 512;
    int arx = arow & 7;

    int bcode = (lane & 7) + ((lane >> 4) & 1) * 8;
    int bkg   = (lane >> 3) & 1;
    unsigned b_base[2];
    #pragma unroll
    for (int n2 = 0; n2 < 2; n2++)
        b_base[n2] = ws_u + (wn * 32 + n2 * 16 + bcode) * 512;
    int brx = bcode & 7;

    int row_s[4];
    #pragma unroll
    for (int s = 0; s < 4; s++)
        row_s[s] = wm * 32 + (s >> 1) * 16 + (lane >> 2) + (s & 1) * 8;

    for (int cc = 0; cc < 16; cc++) {
        // ---- load w chunk (64 codes x 256 k) ----
        #pragma unroll
        for (int it = 0; it < 8; it++) {
            int flat = t + 256 * it;
            int cl = flat >> 5, gq = flat & 31;
            uint4 v = reinterpret_cast<const uint4*>(
                g_wbf + (size_t)(cc * 64 + cl) * C_)[gq];
            *reinterpret_cast<uint4*>(
                reinterpret_cast<char*>(ws) + cl * 512 + ((gq ^ (cl & 7)) * 16)) = v;
        }
        __syncthreads();

        float d[2][4][4];
        #pragma unroll
        for (int mt = 0; mt < 2; mt++)
            #pragma unroll
            for (int nt = 0; nt < 4; nt++)
                #pragma unroll
                for (int r = 0; r < 4; r++) d[mt][nt][r] = 0.f;

        #pragma unroll 4
        for (int ks = 0; ks < 16; ks++) {
            unsigned a[2][4], bf[2][4];
            #pragma unroll
            for (int mt = 0; mt < 2; mt++) {
                unsigned g = (unsigned)((2 * ks + acg) ^ arx);
                ldm4(a[mt], a_base[mt] + g * 16);
            }
            #pragma unroll
            for (int n2 = 0; n2 < 2; n2++) {
                unsigned g = (unsigned)((2 * ks + bkg) ^ brx);
                ldm4(bf[n2], b_base[n2] + g * 16);
            }
            #pragma unroll
            for (int mt = 0; mt < 2; mt++)
                #pragma unroll
                for (int nt = 0; nt < 4; nt++)
                    mma16816(d[mt][nt], a[mt],
                             bf[nt >> 1][(nt & 1) * 2], bf[nt >> 1][(nt & 1) * 2 + 1]);
        }

        // ---- h = fmaf(-2,dot,c) in place; per-row chunk min ----
        float rmin[4] = {3.4e38f, 3.4e38f, 3.4e38f, 3.4e38f};
        #pragma unroll
        for (int mt = 0; mt < 2; mt++)
            #pragma unroll
            for (int nt = 0; nt < 4; nt++)
                #pragma unroll
                for (int r = 0; r < 4; r++) {
                    int j = cc * 64 + wn * 32 + nt * 8 + 2 * (lane & 3) + (r & 1);
                    float h = fmaf(-2.f, d[mt][nt][r], cs[j]);
                    d[mt][nt][r] = h;
                    rmin[mt * 2 + (r >> 1)] = fminf(rmin[mt * 2 + (r >> 1)], h);
                }
        #pragma unroll
        for (int s = 0; s < 4; s++) {
            float m = rmin[s];
            m = fminf(m, __shfl_xor_sync(0xffffffffu, m, 1));
            m = fminf(m, __shfl_xor_sync(0xffffffffu, m, 2));
            if ((lane & 3) == 0) atomicMin(&minkey[row_s[s]], fkey(m));
        }
        __syncthreads();   // publish minkey; also: all mma reads of ws done

        // ---- append candidates (j, h) to gmem vs running prefix min ----
        float thr[4];
        #pragma unroll
        for (int s = 0; s < 4; s++) thr[s] = unfkey(minkey[row_s[s]]) + MARGIN;
        #pragma unroll
        for (int mt = 0; mt < 2; mt++)
            #pragma unroll
            for (int nt = 0; nt < 4; nt++)
                #pragma unroll
                for (int r = 0; r < 4; r++) {
                    int s = mt * 2 + (r >> 1);
                    float h = d[mt][nt][r];
                    if (h <= thr[s]) {
                        int p = row_s[s];
                        int j = cc * 64 + wn * 32 + nt * 8 + 2 * (lane & 3) + (r & 1);
                        int sl = atomicAdd(&cnt_s[p], 1);
                        if (sl < CANDCAP) {
                            size_t o = (size_t)(pixbase + p) * CANDCAP + sl;
                            g_candj[o] = (short)j;
                            g_candh[o] = h;
                        }
                    }
                }
        if (cc < 15) __syncthreads();
    }

    // ---- emit counts + final threshold ----
    __syncthreads();
    if (t < 128) {
        int pix = pixbase + t;
        int c = cnt_s[t];
        g_ccnt[pix] = (c > CANDCAP) ? NCODE : c;
        g_minh[pix] = unfkey(minkey[t]) + MARGIN;
    }
}

// ---------------------------------------------------------------------------
// Exact rescreen (round-8/9 verbatim): filter vs final threshold, then
// sequential-k fp32 fmaf dot, d2 = fl(fmaf(-2,dot,a)+c), lexicographic (d2,j).
// ---------------------------------------------------------------------------
__global__ void __launch_bounds__(256, 4)
s2_kernel(const float* __restrict__ wt, float* __restrict__ out_idx,
          int write_idx) {
    __shared__ float sd[256];
    __shared__ int   sj[256];
    int t = threadIdx.x;
    int pix = blockIdx.x * 32 + (t >> 3);
    int sl = t & 7;

    int cnt = g_ccnt[pix];
    const float4* xr = reinterpret_cast<const float4*>(g_xT + (size_t)pix * C_);
    float a = g_a[pix];
    float bd = 3.4e38f;
    int   bj = 1 << 30;

    if (cnt <= CANDCAP) {
        float thr = g_minh[pix];
        for (int s = sl; s < cnt; s += 8) {
            size_t o = (size_t)pix * CANDCAP + s;
            float h = g_candh[o];
            if (h > thr) continue;                 // final-min filter
            int j = g_candj[o];
            const float4* wr = reinterpret_cast<const float4*>(wt + (size_t)j * C_);
            float dot = 0.f;
            #pragma unroll 8
            for (int q = 0; q < 64; q++) {
                float4 xv = xr[q], wv = wr[q];
                dot = fmaf(xv.x, wv.x, dot);
                dot = fmaf(xv.y, wv.y, dot);
                dot = fmaf(xv.z, wv.z, dot);
                dot = fmaf(xv.w, wv.w, dot);
            }
            float d2 = __fadd_rn(fmaf(-2.f, dot, a), g_c[j]);
            if (d2 < bd || (d2 == bd && j < bj)) { bd = d2; bj = j; }
        }
    } else {  // safety net: exact full scan (raw overflow, ~never)
        for (int j = sl; j < NCODE; j += 8) {
            const float4* wr = reinterpret_cast<const float4*>(wt + (size_t)j * C_);
            float dot = 0.f;
            #pragma unroll 8
            for (int q = 0; q < 64; q++) {
                float4 xv = xr[q], wv = wr[q];
                dot = fmaf(xv.x, wv.x, dot);
                dot = fmaf(xv.y, wv.y, dot);
                dot = fmaf(xv.z, wv.z, dot);
                dot = fmaf(xv.w, wv.w, dot);
            }
            float d2 = __fadd_rn(fmaf(-2.f, dot, a), g_c[j]);
            if (d2 < bd || (d2 == bd && j < bj)) { bd = d2; bj = j; }
        }
    }
    sd[t] = bd; sj[t] = bj;
    __syncthreads();
    if (sl == 0) {
        #pragma unroll
        for (int k = 1; k < 8; k++) {
            float d = sd[t + k]; int j = sj[t + k];
            if (d < bd || (d == bd && j < bj)) { bd = d; bj = j; }
        }
        g_idx[pix] = bj;
        if (write_idx) out_idx[pix] = (float)bj;
    }
}

// ---------------------------------------------------------------------------
// Scatter (round-9 verbatim): 512 threads, q = w[idx], ste = fl(fl(q-x)+x)
// ---------------------------------------------------------------------------
__global__ void __launch_bounds__(512, 1)
scatter_kernel(const float* __restrict__ x, const float* __restrict__ wt,
               float* __restrict__ out_q, float* __restrict__ out_ste,
               int has_ste) {
    extern __shared__ float sm[];          // [256][129]
    __shared__ int lidx[128];

    int t = threadIdx.x, lane = t & 31, warp = t >> 5;   // warp 0..15
    int pix_base = blockIdx.x * 128;
    int b  = pix_base >> 10;
    int hw = pix_base & 1023;

    if (t < 128) lidx[t] = g_idx[pix_base + t];
    __syncthreads();

    for (int rit = 0; rit < 8; rit++) {
        int r = warp + 16 * rit;
        const float* row = wt + (size_t)lidx[r] * C_;
        #pragma unroll
        for (int kit = 0; kit < 8; kit++) {
            int ci = lane + 32 * kit;
            sm[ci * 129 + r] = row[ci];
        }
    }
    __syncthreads();

    int hw_l = t & 127;
    int ch   = t >> 7;                     // 0..3
    for (int cit = 0; cit < 64; cit++) {
        int ci = ch + 4 * cit;
        size_t o = (size_t)b * C_ * HW_ + (size_t)ci * HW_ + hw + hw_l;
        float q = sm[ci * 129 + hw_l];
        out_q[o] = q;
        if (has_ste) {
            float xv = x[o];
            out_ste[o] = __fadd_rn(__fsub_rn(q, xv), xv);
        }
    }
}

// ---------------------------------------------------------------------------
extern "C" void kernel_launch(void* const* d_in, const int* in_sizes, int n_in,
                              void* d_out, int out_size) {
    const float* x  = (const float*)d_in[0];
    const float* wt = (const float*)d_in[1];
    float* out = (float*)d_out;

    const long long qsz = (long long)NPIX * C_;
    int has_ste = (out_size >= (int)(2 * qsz)) ? 1 : 0;
    int has_idx = (out_size >= (int)(2 * qsz) + NPIX) ||
                  (out_size == (int)qsz + NPIX);
    float* out_q   = out;
    float* out_ste = out + qsz;
    float* out_idx = has_ste ? out + 2 * qsz : out + qsz;

    // Lazily-created side stream + events (resources, not work; the launched
    // work is identical and deterministic on every call).
    static cudaStream_t side = nullptr;
    static cudaEvent_t  efork = nullptr, ejoin = nullptr;
    if (side == nullptr) {
        cudaStreamCreateWithFlags(&side, cudaStreamNonBlocking);
        cudaEventCreateWithFlags(&efork, cudaEventDisableTiming);
        cudaEventCreateWithFlags(&ejoin, cudaEventDisableTiming);
    }

    cudaFuncSetAttribute(t_bf_kernel,
        cudaFuncAttributeMaxDynamicSharedMemorySize, 256 * 132 * 4);
    cudaFuncSetAttribute(t_fp_kernel,
        cudaFuncAttributeMaxDynamicSharedMemorySize, 256 * 132 * 4);
    cudaFuncSetAttribute(g_kernel,
        cudaFuncAttributeMaxDynamicSharedMemorySize, 98304);
    cudaFuncSetAttribute(scatter_kernel,
        cudaFuncAttributeMaxDynamicSharedMemorySize, 132096);

    // fork: side branch computes g_xT + g_a (needed only by s2)
    cudaEventRecord(efork, 0);
    cudaStreamWaitEvent(side, efork, 0);
    t_fp_kernel<<<NPIX / 128, 512, 256 * 132 * 4, side>>>(x);
    cudaEventRecord(ejoin, side);

    // main branch: critical path to g
    c_kernel<<<4, 256>>>(wt);
    wcvt_kernel<<<NCODE * C_ / 2 / 256, 256>>>(wt);
    t_bf_kernel<<<NPIX / 128, 512, 256 * 132 * 4>>>(x);
    g_kernel<<<NPIX / 128, 256, 98304>>>();

    // join before s2 (needs g_xT, g_a)
    cudaStreamWaitEvent(0, ejoin, 0);
    s2_kernel<<<NPIX / 32, 256>>>(wt, out_idx, has_idx ? 1 : 0);
    scatter_kernel<<<NPIX / 128, 512, 132096>>>(x, wt, out_q, out_ste, has_ste);
}

// round 14
// speedup vs baseline: 1.5442x; 1.1293x over previous
#include <cuda_runtime.h>
#include <cuda_bf16.h>
#include <cuda_fp16.h>

#define B_      64
#define C_      256
#define HW_     1024
#define NPIX    65536
#define NCODE   1024
#define CANDCAP 32
#define MARGIN  1e-3f

__device__ float g_a[NPIX];
__device__ float g_c[NCODE];
__device__ int   g_idx[NPIX];
__device__ unsigned short g_xbf[(size_t)NPIX * C_];   // bf16 x, pixel-major
__device__ unsigned short g_wbf[NCODE * C_];          // bf16 codebook
__device__ short g_candj[(size_t)NPIX * CANDCAP];
__device__ float g_candh[(size_t)NPIX * CANDCAP];
__device__ float g_minh[NPIX];                        // final_min + MARGIN
__device__ int   g_ccnt[NPIX];

// monotone float<->uint key for atomicMin on signed floats
__device__ __forceinline__ unsigned fkey(float f) {
    unsigned u = __float_as_uint(f);
    return (u & 0x80000000u) ? ~u : (u | 0x80000000u);
}
__device__ __forceinline__ float unfkey(unsigned k) {
    unsigned u = (k & 0x80000000u) ? (k & 0x7fffffffu) : ~k;
    return __uint_as_float(u);
}

__device__ __forceinline__ void ldm4(unsigned* r, unsigned addr) {
    asm volatile("ldmatrix.sync.aligned.m8n8.x4.shared.b16 {%0,%1,%2,%3}, [%4];"
                 : "=r"(r[0]), "=r"(r[1]), "=r"(r[2]), "=r"(r[3]) : "r"(addr));
}
__device__ __forceinline__ void mma16816(float* d, const unsigned* a,
                                         unsigned b0, unsigned b1) {
    asm volatile(
        "mma.sync.aligned.m16n8k16.row.col.f32.bf16.bf16.f32 "
        "{%0,%1,%2,%3}, {%4,%5,%6,%7}, {%8,%9}, {%0,%1,%2,%3};"
        : "+f"(d[0]), "+f"(d[1]), "+f"(d[2]), "+f"(d[3])
        : "r"(a[0]), "r"(a[1]), "r"(a[2]), "r"(a[3]), "r"(b0), "r"(b1));
}

// ---------------------------------------------------------------------------
// c_j = sum fl(w^2) sequential (exact, matches reference rounding model)
// ---------------------------------------------------------------------------
__global__ void c_kernel(const float* __restrict__ w) {
    int j = blockIdx.x * blockDim.x + threadIdx.x;
    if (j < NCODE) {
        const float* r = w + (size_t)j * C_;
        float s = 0.f;
        #pragma unroll 8
        for (int i = 0; i < C_; i++) s = __fadd_rn(s, __fmul_rn(r[i], r[i]));
        g_c[j] = s;
    }
}

// ---------------------------------------------------------------------------
// codebook -> bf16
// ---------------------------------------------------------------------------
__global__ void wcvt_kernel(const float* __restrict__ w) {
    int i = blockIdx.x * blockDim.x + threadIdx.x;   // over pairs
    if (i < NCODE * C_ / 2) {
        float2 v = reinterpret_cast<const float2*>(w)[i];
        __nv_bfloat162 b2 = __floats2bfloat162_rn(v.x, v.y);
        reinterpret_cast<unsigned*>(g_wbf)[i] = *reinterpret_cast<unsigned*>(&b2);
    }
}

// ---------------------------------------------------------------------------
// t_bf: x (B,C,H,W) -> bf16 pixel-major g_xbf + a_p = sum fl(x^2) sequential.
// (round-9 t_kernel minus the fp32 g_xT store; arithmetic verbatim)
// ---------------------------------------------------------------------------
__global__ void __launch_bounds__(512, 1)
t_bf_kernel(const float* __restrict__ x) {
    extern __shared__ float sm[];                    // [256][132]
    int t = threadIdx.x;
    int pixbase = blockIdx.x * 128;
    int b  = pixbase >> 10;
    int hw0 = pixbase & 1023;
    const float* xb = x + (size_t)b * C_ * HW_ + hw0;

    #pragma unroll 8
    for (int it = 0; it < 16; it++) {
        int idx = t + 512 * it;
        int c = idx >> 5, hq = idx & 31;
        float4 v = *reinterpret_cast<const float4*>(xb + (size_t)c * HW_ + 4 * hq);
        *reinterpret_cast<float4*>(&sm[c * 132 + 4 * hq]) = v;
    }
    __syncthreads();

    if (t < 128) {
        float s = 0.f;
        for (int k = 0; k < C_; k++) {
            float v = sm[k * 132 + t];
            s = __fadd_rn(s, __fmul_rn(v, v));
        }
        g_a[pixbase + t] = s;
    }

    #pragma unroll 4
    for (int it = 0; it < 16; it++) {
        int idx = t + 512 * it;
        int pl = idx >> 6, kq = idx & 63;
        float v0 = sm[(4 * kq + 0) * 132 + pl];
        float v1 = sm[(4 * kq + 1) * 132 + pl];
        float v2 = sm[(4 * kq + 2) * 132 + pl];
        float v3 = sm[(4 * kq + 3) * 132 + pl];
        size_t o = (size_t)(pixbase + pl) * C_ + 4 * kq;
        __nv_bfloat162 b01 = __floats2bfloat162_rn(v0, v1);
        __nv_bfloat162 b23 = __floats2bfloat162_rn(v2, v3);
        uint2 u = make_uint2(*reinterpret_cast<unsigned*>(&b01),
                             *reinterpret_cast<unsigned*>(&b23));
        *reinterpret_cast<uint2*>(g_xbf + o) = u;
    }
}

// ---------------------------------------------------------------------------
// bf16 MMA screen (rounds 8/9 VERBATIM). Online candidate collection into
// GMEM (j, h pairs) + final threshold.
// ---------------------------------------------------------------------------
__global__ void __launch_bounds__(256, 2)
g_kernel() {
    extern __shared__ unsigned short smem_g[];
    unsigned short* xs = smem_g;               // [128][256] swizzled, 64KB
    unsigned short* ws = smem_g + 128 * 256;   // [64][256]  swizzled, 32KB
    __shared__ float    cs[NCODE];
    __shared__ unsigned minkey[128];
    __shared__ int      cnt_s[128];

    int t = threadIdx.x, lane = t & 31, wid = t >> 5;
    int wm = wid >> 1, wn = wid & 1;
    int pixbase = blockIdx.x * 128;

    for (int i = t; i < NCODE; i += 256) cs[i] = g_c[i];
    if (t < 128) { minkey[t] = fkey(3.4e38f); cnt_s[t] = 0; }

    // load x tile (16B granules, XOR-swizzled by row&7)
    #pragma unroll 4
    for (int it = 0; it < 16; it++) {
        int flat = t + 256 * it;
        int pl = flat >> 5, gq = flat & 31;
        uint4 v = reinterpret_cast<const uint4*>(
            g_xbf + (size_t)(pixbase + pl) * C_)[gq];
        *reinterpret_cast<uint4*>(
            reinterpret_cast<char*>(xs) + pl * 512 + ((gq ^ (pl & 7)) * 16)) = v;
    }

    unsigned xs_u = (unsigned)__cvta_generic_to_shared(xs);
    unsigned ws_u = (unsigned)__cvta_generic_to_shared(ws);

    int asub = lane >> 3;
    int arow = (asub & 1) * 8 + (lane & 7);
    int acg  = asub >> 1;
    unsigned a_base[2];
    #pragma unroll
    for (int mt = 0; mt < 2; mt++)
        a_base[mt] = xs_u + (wm * 32 + mt * 16 + arow) * 512;
    int arx = arow & 7;

    int bcode = (lane & 7) + ((lane >> 4) & 1) * 8;
    int bkg   = (lane >> 3) & 1;
    unsigned b_base[2];
    #pragma unroll
    for (int n2 = 0; n2 < 2; n2++)
        b_base[n2] = ws_u + (wn * 32 + n2 * 16 + bcode) * 512;
    int brx = bcode & 7;

    int row_s[4];
    #pragma unroll
    for (int s = 0; s < 4; s++)
        row_s[s] = wm * 32 + (s >> 1) * 16 + (lane >> 2) + (s & 1) * 8;

    for (int cc = 0; cc < 16; cc++) {
        // ---- load w chunk (64 codes x 256 k) ----
        #pragma unroll
        for (int it = 0; it < 8; it++) {
            int flat = t + 256 * it;
            int cl = flat >> 5, gq = flat & 31;
            uint4 v = reinterpret_cast<const uint4*>(
                g_wbf + (size_t)(cc * 64 + cl) * C_)[gq];
            *reinterpret_cast<uint4*>(
                reinterpret_cast<char*>(ws) + cl * 512 + ((gq ^ (cl & 7)) * 16)) = v;
        }
        __syncthreads();

        float d[2][4][4];
        #pragma unroll
        for (int mt = 0; mt < 2; mt++)
            #pragma unroll
            for (int nt = 0; nt < 4; nt++)
                #pragma unroll
                for (int r = 0; r < 4; r++) d[mt][nt][r] = 0.f;

        #pragma unroll 4
        for (int ks = 0; ks < 16; ks++) {
            unsigned a[2][4], bf[2][4];
            #pragma unroll
            for (int mt = 0; mt < 2; mt++) {
                unsigned g = (unsigned)((2 * ks + acg) ^ arx);
                ldm4(a[mt], a_base[mt] + g * 16);
            }
            #pragma unroll
            for (int n2 = 0; n2 < 2; n2++) {
                unsigned g = (unsigned)((2 * ks + bkg) ^ brx);
                ldm4(bf[n2], b_base[n2] + g * 16);
            }
            #pragma unroll
            for (int mt = 0; mt < 2; mt++)
                #pragma unroll
                for (int nt = 0; nt < 4; nt++)
                    mma16816(d[mt][nt], a[mt],
                             bf[nt >> 1][(nt & 1) * 2], bf[nt >> 1][(nt & 1) * 2 + 1]);
        }

        // ---- h = fmaf(-2,dot,c) in place; per-row chunk min ----
        float rmin[4] = {3.4e38f, 3.4e38f, 3.4e38f, 3.4e38f};
        #pragma unroll
        for (int mt = 0; mt < 2; mt++)
            #pragma unroll
            for (int nt = 0; nt < 4; nt++)
                #pragma unroll
                for (int r = 0; r < 4; r++) {
                    int j = cc * 64 + wn * 32 + nt * 8 + 2 * (lane & 3) + (r & 1);
                    float h = fmaf(-2.f, d[mt][nt][r], cs[j]);
                    d[mt][nt][r] = h;
                    rmin[mt * 2 + (r >> 1)] = fminf(rmin[mt * 2 + (r >> 1)], h);
                }
        #pragma unroll
        for (int s = 0; s < 4; s++) {
            float m = rmin[s];
            m = fminf(m, __shfl_xor_sync(0xffffffffu, m, 1));
            m = fminf(m, __shfl_xor_sync(0xffffffffu, m, 2));
            if ((lane & 3) == 0) atomicMin(&minkey[row_s[s]], fkey(m));
        }
        __syncthreads();   // publish minkey; also: all mma reads of ws done

        // ---- append candidates (j, h) to gmem vs running prefix min ----
        float thr[4];
        #pragma unroll
        for (int s = 0; s < 4; s++) thr[s] = unfkey(minkey[row_s[s]]) + MARGIN;
        #pragma unroll
        for (int mt = 0; mt < 2; mt++)
            #pragma unroll
            for (int nt = 0; nt < 4; nt++)
                #pragma unroll
                for (int r = 0; r < 4; r++) {
                    int s = mt * 2 + (r >> 1);
                    float h = d[mt][nt][r];
                    if (h <= thr[s]) {
                        int p = row_s[s];
                        int j = cc * 64 + wn * 32 + nt * 8 + 2 * (lane & 3) + (r & 1);
                        int sl = atomicAdd(&cnt_s[p], 1);
                        if (sl < CANDCAP) {
                            size_t o = (size_t)(pixbase + p) * CANDCAP + sl;
                            g_candj[o] = (short)j;
                            g_candh[o] = h;
                        }
                    }
                }
        if (cc < 15) __syncthreads();
    }

    // ---- emit counts + final threshold ----
    __syncthreads();
    if (t < 128) {
        int pix = pixbase + t;
        int c = cnt_s[t];
        g_ccnt[pix] = (c > CANDCAP) ? NCODE : c;
        g_minh[pix] = unfkey(minkey[t]) + MARGIN;
    }
}

// ---------------------------------------------------------------------------
// Exact rescreen: block covers 32 consecutive pixels (same image, contiguous
// hw) -> x is loaded DIRECTLY from its original layout, fully coalesced, into
// a stride-257 smem tile. Arithmetic verbatim round-1: sequential-k fp32
// fmaf dot, d2 = fl(fmaf(-2,dot,a)+c), lexicographic (d2,j).
// ---------------------------------------------------------------------------
__global__ void __launch_bounds__(256, 4)
s2_kernel(const float* __restrict__ x, const float* __restrict__ wt,
          float* __restrict__ out_idx, int write_idx) {
    __shared__ float xsm[32 * 257];        // [pixel][k], stride 257: no conflicts
    __shared__ float sd[256];
    __shared__ int   sj[256];
    int t = threadIdx.x, lane = t & 31;
    int pix_base = blockIdx.x * 32;
    int b   = pix_base >> 10;
    int hw0 = pix_base & 1023;
    const float* xb = x + (size_t)b * C_ * HW_ + hw0;

    // load 256 k x 32 hw: each iteration, 8 warp-rows of k, 32 lanes = 32 hw
    int krow = t >> 5;
    #pragma unroll 8
    for (int it = 0; it < 32; it++) {
        int k = krow + 8 * it;
        xsm[lane * 257 + k] = xb[(size_t)k * HW_ + lane];
    }
    __syncthreads();

    int p   = t >> 3;
    int pix = pix_base + p;
    int sl  = t & 7;
    int cnt = g_ccnt[pix];
    const float* xr = &xsm[p * 257];
    float a = g_a[pix];
    float bd = 3.4e38f;
    int   bj = 1 << 30;

    if (cnt <= CANDCAP) {
        float thr = g_minh[pix];
        for (int s = sl; s < cnt; s += 8) {
            size_t o = (size_t)pix * CANDCAP + s;
            float h = g_candh[o];
            if (h > thr) continue;                 // final-min filter
            int j = g_candj[o];
            const float4* wr = reinterpret_cast<const float4*>(wt + (size_t)j * C_);
            float dot = 0.f;
            #pragma unroll 8
            for (int q = 0; q < 64; q++) {
                float4 wv = wr[q];
                dot = fmaf(xr[4 * q + 0], wv.x, dot);
                dot = fmaf(xr[4 * q + 1], wv.y, dot);
                dot = fmaf(xr[4 * q + 2], wv.z, dot);
                dot = fmaf(xr[4 * q + 3], wv.w, dot);
            }
            float d2 = __fadd_rn(fmaf(-2.f, dot, a), g_c[j]);
            if (d2 < bd || (d2 == bd && j < bj)) { bd = d2; bj = j; }
        }
    } else {  // safety net: exact full scan (raw overflow, ~never)
        for (int j = sl; j < NCODE; j += 8) {
            const float4* wr = reinterpret_cast<const float4*>(wt + (size_t)j * C_);
            float dot = 0.f;
            #pragma unroll 8
            for (int q = 0; q < 64; q++) {
                float4 wv = wr[q];
                dot = fmaf(xr[4 * q + 0], wv.x, dot);
                dot = fmaf(xr[4 * q + 1], wv.y, dot);
                dot = fmaf(xr[4 * q + 2], wv.z, dot);
                dot = fmaf(xr[4 * q + 3], wv.w, dot);
            }
            float d2 = __fadd_rn(fmaf(-2.f, dot, a), g_c[j]);
            if (d2 < bd || (d2 == bd && j < bj)) { bd = d2; bj = j; }
        }
    }
    sd[t] = bd; sj[t] = bj;
    __syncthreads();
    if (sl == 0) {
        #pragma unroll
        for (int k = 1; k < 8; k++) {
            float d = sd[t + k]; int j = sj[t + k];
            if (d < bd || (d == bd && j < bj)) { bd = d; bj = j; }
        }
        g_idx[pix] = bj;
        if (write_idx) out_idx[pix] = (float)bj;
    }
}

// ---------------------------------------------------------------------------
// Scatter (round-9 verbatim): 512 threads, q = w[idx], ste = fl(fl(q-x)+x)
// ---------------------------------------------------------------------------
__global__ void __launch_bounds__(512, 1)
scatter_kernel(const float* __restrict__ x, const float* __restrict__ wt,
               float* __restrict__ out_q, float* __restrict__ out_ste,
               int has_ste) {
    extern __shared__ float sm[];          // [256][129]
    __shared__ int lidx[128];

    int t = threadIdx.x, lane = t & 31, warp = t >> 5;   // warp 0..15
    int pix_base = blockIdx.x * 128;
    int b  = pix_base >> 10;
    int hw = pix_base & 1023;

    if (t < 128) lidx[t] = g_idx[pix_base + t];
    __syncthreads();

    for (int rit = 0; rit < 8; rit++) {
        int r = warp + 16 * rit;
        const float* row = wt + (size_t)lidx[r] * C_;
        #pragma unroll
        for (int kit = 0; kit < 8; kit++) {
            int ci = lane + 32 * kit;
            sm[ci * 129 + r] = row[ci];
        }
    }
    __syncthreads();

    int hw_l = t & 127;
    int ch   = t >> 7;                     // 0..3
    for (int cit = 0; cit < 64; cit++) {
        int ci = ch + 4 * cit;
        size_t o = (size_t)b * C_ * HW_ + (size_t)ci * HW_ + hw + hw_l;
        float q = sm[ci * 129 + hw_l];
        out_q[o] = q;
        if (has_ste) {
            float xv = x[o];
            out_ste[o] = __fadd_rn(__fsub_rn(q, xv), xv);
        }
    }
}

// ---------------------------------------------------------------------------
extern "C" void kernel_launch(void* const* d_in, const int* in_sizes, int n_in,
                              void* d_out, int out_size) {
    const float* x  = (const float*)d_in[0];
    const float* wt = (const float*)d_in[1];
    float* out = (float*)d_out;

    const long long qsz = (long long)NPIX * C_;
    int has_ste = (out_size >= (int)(2 * qsz)) ? 1 : 0;
    int has_idx = (out_size >= (int)(2 * qsz) + NPIX) ||
                  (out_size == (int)qsz + NPIX);
    float* out_q   = out;
    float* out_ste = out + qsz;
    float* out_idx = has_ste ? out + 2 * qsz : out + qsz;

    cudaFuncSetAttribute(t_bf_kernel,
        cudaFuncAttributeMaxDynamicSharedMemorySize, 256 * 132 * 4);
    cudaFuncSetAttribute(g_kernel,
        cudaFuncAttributeMaxDynamicSharedMemorySize, 98304);
    cudaFuncSetAttribute(scatter_kernel,
        cudaFuncAttributeMaxDynamicSharedMemorySize, 132096);

    c_kernel<<<4, 256>>>(wt);
    wcvt_kernel<<<NCODE * C_ / 2 / 256, 256>>>(wt);
    t_bf_kernel<<<NPIX / 128, 512, 256 * 132 * 4>>>(x);
    g_kernel<<<NPIX / 128, 256, 98304>>>();
    s2_kernel<<<NPIX / 32, 256>>>(x, wt, out_idx, has_idx ? 1 : 0);
    scatter_kernel<<<NPIX / 128, 512, 132096>>>(x, wt, out_q, out_ste, has_ste);
}

// round 15
// speedup vs baseline: 1.6577x; 1.0735x over previous
#include <cuda_runtime.h>
#include <cuda_bf16.h>
#include <cuda_fp16.h>

#define B_      64
#define C_      256
#define HW_     1024
#define NPIX    65536
#define NCODE   1024
#define CANDCAP 32
#define MARGIN  1e-3f

__device__ float g_a[NPIX];
__device__ float g_c[NCODE];
__device__ unsigned short g_xbf[(size_t)NPIX * C_];   // bf16 x, pixel-major
__device__ unsigned short g_wbf[NCODE * C_];          // bf16 codebook
__device__ short g_candj[(size_t)NPIX * CANDCAP];
__device__ float g_candh[(size_t)NPIX * CANDCAP];
__device__ float g_minh[NPIX];                        // final_min + MARGIN
__device__ int   g_ccnt[NPIX];

// monotone float<->uint key for atomicMin on signed floats
__device__ __forceinline__ unsigned fkey(float f) {
    unsigned u = __float_as_uint(f);
    return (u & 0x80000000u) ? ~u : (u | 0x80000000u);
}
__device__ __forceinline__ float unfkey(unsigned k) {
    unsigned u = (k & 0x80000000u) ? (k & 0x7fffffffu) : ~k;
    return __uint_as_float(u);
}

__device__ __forceinline__ void ldm4(unsigned* r, unsigned addr) {
    asm volatile("ldmatrix.sync.aligned.m8n8.x4.shared.b16 {%0,%1,%2,%3}, [%4];"
                 : "=r"(r[0]), "=r"(r[1]), "=r"(r[2]), "=r"(r[3]) : "r"(addr));
}
__device__ __forceinline__ void mma16816(float* d, const unsigned* a,
                                         unsigned b0, unsigned b1) {
    asm volatile(
        "mma.sync.aligned.m16n8k16.row.col.f32.bf16.bf16.f32 "
        "{%0,%1,%2,%3}, {%4,%5,%6,%7}, {%8,%9}, {%0,%1,%2,%3};"
        : "+f"(d[0]), "+f"(d[1]), "+f"(d[2]), "+f"(d[3])
        : "r"(a[0]), "r"(a[1]), "r"(a[2]), "r"(a[3]), "r"(b0), "r"(b1));
}

// ---------------------------------------------------------------------------
// c_j = sum fl(w^2) sequential (exact, matches reference rounding model)
// ---------------------------------------------------------------------------
__global__ void c_kernel(const float* __restrict__ w) {
    int j = blockIdx.x * blockDim.x + threadIdx.x;
    if (j < NCODE) {
        const float* r = w + (size_t)j * C_;
        float s = 0.f;
        #pragma unroll 8
        for (int i = 0; i < C_; i++) s = __fadd_rn(s, __fmul_rn(r[i], r[i]));
        g_c[j] = s;
    }
}

// ---------------------------------------------------------------------------
// codebook -> bf16
// ---------------------------------------------------------------------------
__global__ void wcvt_kernel(const float* __restrict__ w) {
    int i = blockIdx.x * blockDim.x + threadIdx.x;   // over pairs
    if (i < NCODE * C_ / 2) {
        float2 v = reinterpret_cast<const float2*>(w)[i];
        __nv_bfloat162 b2 = __floats2bfloat162_rn(v.x, v.y);
        reinterpret_cast<unsigned*>(g_wbf)[i] = *reinterpret_cast<unsigned*>(&b2);
    }
}

// ---------------------------------------------------------------------------
// t_bf: x (B,C,H,W) -> bf16 pixel-major g_xbf + a_p = sum fl(x^2) sequential.
// (round-14 verbatim)
// ---------------------------------------------------------------------------
__global__ void __launch_bounds__(512, 1)
t_bf_kernel(const float* __restrict__ x) {
    extern __shared__ float sm[];                    // [256][132]
    int t = threadIdx.x;
    int pixbase = blockIdx.x * 128;
    int b  = pixbase >> 10;
    int hw0 = pixbase & 1023;
    const float* xb = x + (size_t)b * C_ * HW_ + hw0;

    #pragma unroll 8
    for (int it = 0; it < 16; it++) {
        int idx = t + 512 * it;
        int c = idx >> 5, hq = idx & 31;
        float4 v = *reinterpret_cast<const float4*>(xb + (size_t)c * HW_ + 4 * hq);
        *reinterpret_cast<float4*>(&sm[c * 132 + 4 * hq]) = v;
    }
    __syncthreads();

    if (t < 128) {
        float s = 0.f;
        for (int k = 0; k < C_; k++) {
            float v = sm[k * 132 + t];
            s = __fadd_rn(s, __fmul_rn(v, v));
        }
        g_a[pixbase + t] = s;
    }

    #pragma unroll 4
    for (int it = 0; it < 16; it++) {
        int idx = t + 512 * it;
        int pl = idx >> 6, kq = idx & 63;
        float v0 = sm[(4 * kq + 0) * 132 + pl];
        float v1 = sm[(4 * kq + 1) * 132 + pl];
        float v2 = sm[(4 * kq + 2) * 132 + pl];
        float v3 = sm[(4 * kq + 3) * 132 + pl];
        size_t o = (size_t)(pixbase + pl) * C_ + 4 * kq;
        __nv_bfloat162 b01 = __floats2bfloat162_rn(v0, v1);
        __nv_bfloat162 b23 = __floats2bfloat162_rn(v2, v3);
        uint2 u = make_uint2(*reinterpret_cast<unsigned*>(&b01),
                             *reinterpret_cast<unsigned*>(&b23));
        *reinterpret_cast<uint2*>(g_xbf + o) = u;
    }
}

// ---------------------------------------------------------------------------
// bf16 MMA screen (rounds 8/9/14 VERBATIM). Online candidate collection into
// GMEM (j, h pairs) + final threshold.
// ---------------------------------------------------------------------------
__global__ void __launch_bounds__(256, 2)
g_kernel() {
    extern __shared__ unsigned short smem_g[];
    unsigned short* xs = smem_g;               // [128][256] swizzled, 64KB
    unsigned short* ws = smem_g + 128 * 256;   // [64][256]  swizzled, 32KB
    __shared__ float    cs[NCODE];
    __shared__ unsigned minkey[128];
    __shared__ int      cnt_s[128];

    int t = threadIdx.x, lane = t & 31, wid = t >> 5;
    int wm = wid >> 1, wn = wid & 1;
    int pixbase = blockIdx.x * 128;

    for (int i = t; i < NCODE; i += 256) cs[i] = g_c[i];
    if (t < 128) { minkey[t] = fkey(3.4e38f); cnt_s[t] = 0; }

    // load x tile (16B granules, XOR-swizzled by row&7)
    #pragma unroll 4
    for (int it = 0; it < 16; it++) {
        int flat = t + 256 * it;
        int pl = flat >> 5, gq = flat & 31;
        uint4 v = reinterpret_cast<const uint4*>(
            g_xbf + (size_t)(pixbase + pl) * C_)[gq];
        *reinterpret_cast<uint4*>(
            reinterpret_cast<char*>(xs) + pl * 512 + ((gq ^ (pl & 7)) * 16)) = v;
    }

    unsigned xs_u = (unsigned)__cvta_generic_to_shared(xs);
    unsigned ws_u = (unsigned)__cvta_generic_to_shared(ws);

    int asub = lane >> 3;
    int arow = (asub & 1) * 8 + (lane & 7);
    int acg  = asub >> 1;
    unsigned a_base[2];
    #pragma unroll
    for (int mt = 0; mt < 2; mt++)
        a_base[mt] = xs_u + (wm * 32 + mt * 16 + arow) * 512;
    int arx = arow & 7;

    int bcode = (lane & 7) + ((lane >> 4) & 1) * 8;
    int bkg   = (lane >> 3) & 1;
    unsigned b_base[2];
    #pragma unroll
    for (int n2 = 0; n2 < 2; n2++)
        b_base[n2] = ws_u + (wn * 32 + n2 * 16 + bcode) * 512;
    int brx = bcode & 7;

    int row_s[4];
    #pragma unroll
    for (int s = 0; s < 4; s++)
        row_s[s] = wm * 32 + (s >> 1) * 16 + (lane >> 2) + (s & 1) * 8;

    for (int cc = 0; cc < 16; cc++) {
        // ---- load w chunk (64 codes x 256 k) ----
        #pragma unroll
        for (int it = 0; it < 8; it++) {
            int flat = t + 256 * it;
            int cl = flat >> 5, gq = flat & 31;
            uint4 v = reinterpret_cast<const uint4*>(
                g_wbf + (size_t)(cc * 64 + cl) * C_)[gq];
            *reinterpret_cast<uint4*>(
                reinterpret_cast<char*>(ws) + cl * 512 + ((gq ^ (cl & 7)) * 16)) = v;
        }
        __syncthreads();

        float d[2][4][4];
        #pragma unroll
        for (int mt = 0; mt < 2; mt++)
            #pragma unroll
            for (int nt = 0; nt < 4; nt++)
                #pragma unroll
                for (int r = 0; r < 4; r++) d[mt][nt][r] = 0.f;

        #pragma unroll 4
        for (int ks = 0; ks < 16; ks++) {
            unsigned a[2][4], bf[2][4];
            #pragma unroll
            for (int mt = 0; mt < 2; mt++) {
                unsigned g = (unsigned)((2 * ks + acg) ^ arx);
                ldm4(a[mt], a_base[mt] + g * 16);
            }
            #pragma unroll
            for (int n2 = 0; n2 < 2; n2++) {
                unsigned g = (unsigned)((2 * ks + bkg) ^ brx);
                ldm4(bf[n2], b_base[n2] + g * 16);
            }
            #pragma unroll
            for (int mt = 0; mt < 2; mt++)
                #pragma unroll
                for (int nt = 0; nt < 4; nt++)
                    mma16816(d[mt][nt], a[mt],
                             bf[nt >> 1][(nt & 1) * 2], bf[nt >> 1][(nt & 1) * 2 + 1]);
        }

        // ---- h = fmaf(-2,dot,c) in place; per-row chunk min ----
        float rmin[4] = {3.4e38f, 3.4e38f, 3.4e38f, 3.4e38f};
        #pragma unroll
        for (int mt = 0; mt < 2; mt++)
            #pragma unroll
            for (int nt = 0; nt < 4; nt++)
                #pragma unroll
                for (int r = 0; r < 4; r++) {
                    int j = cc * 64 + wn * 32 + nt * 8 + 2 * (lane & 3) + (r & 1);
                    float h = fmaf(-2.f, d[mt][nt][r], cs[j]);
                    d[mt][nt][r] = h;
                    rmin[mt * 2 + (r >> 1)] = fminf(rmin[mt * 2 + (r >> 1)], h);
                }
        #pragma unroll
        for (int s = 0; s < 4; s++) {
            float m = rmin[s];
            m = fminf(m, __shfl_xor_sync(0xffffffffu, m, 1));
            m = fminf(m, __shfl_xor_sync(0xffffffffu, m, 2));
            if ((lane & 3) == 0) atomicMin(&minkey[row_s[s]], fkey(m));
        }
        __syncthreads();   // publish minkey; also: all mma reads of ws done

        // ---- append candidates (j, h) to gmem vs running prefix min ----
        float thr[4];
        #pragma unroll
        for (int s = 0; s < 4; s++) thr[s] = unfkey(minkey[row_s[s]]) + MARGIN;
        #pragma unroll
        for (int mt = 0; mt < 2; mt++)
            #pragma unroll
            for (int nt = 0; nt < 4; nt++)
                #pragma unroll
                for (int r = 0; r < 4; r++) {
                    int s = mt * 2 + (r >> 1);
                    float h = d[mt][nt][r];
                    if (h <= thr[s]) {
                        int p = row_s[s];
                        int j = cc * 64 + wn * 32 + nt * 8 + 2 * (lane & 3) + (r & 1);
                        int sl = atomicAdd(&cnt_s[p], 1);
                        if (sl < CANDCAP) {
                            size_t o = (size_t)(pixbase + p) * CANDCAP + sl;
                            g_candj[o] = (short)j;
                            g_candh[o] = h;
                        }
                    }
                }
        if (cc < 15) __syncthreads();
    }

    // ---- emit counts + final threshold ----
    __syncthreads();
    if (t < 128) {
        int pix = pixbase + t;
        int c = cnt_s[t];
        g_ccnt[pix] = (c > CANDCAP) ? NCODE : c;
        g_minh[pix] = unfkey(minkey[t]) + MARGIN;
    }
}

// ---------------------------------------------------------------------------
// Fused rescreen + scatter, 32 consecutive pixels per block:
//  1. x tile loaded DIRECTLY from (B,C,H,W), coalesced, into xsm (stride 257)
//  2. exact argmin (verbatim round-1 arithmetic + lexicographic tie-break)
//  3. gather chosen codebook rows transposed into wsm (stride 33)
//  4. write q and ste = fl(fl(q-x)+x) with x FROM SMEM (same bits)
// ---------------------------------------------------------------------------
#define XSM_OFF 0
#define WSM_OFF (32 * 257)
__global__ void __launch_bounds__(256, 3)
s3_kernel(const float* __restrict__ x, const float* __restrict__ wt,
          float* __restrict__ out_q, float* __restrict__ out_ste,
          float* __restrict__ out_idx, int write_idx, int has_ste) {
    extern __shared__ float dynf[];
    float* xsm = dynf + XSM_OFF;           // [32 pix][257]
    float* wsm = dynf + WSM_OFF;           // [256 ch][33]
    __shared__ float sd[256];
    __shared__ int   sj[256];
    __shared__ int   lidx[32];

    int t = threadIdx.x, lane = t & 31, warp = t >> 5;
    int pix_base = blockIdx.x * 32;
    int b   = pix_base >> 10;
    int hw0 = pix_base & 1023;
    const float* xb = x + (size_t)b * C_ * HW_ + hw0;

    // ---- 1. load x tile: 256 k x 32 hw, fully coalesced ----
    #pragma unroll 8
    for (int it = 0; it < 32; it++) {
        int k = warp + 8 * it;
        xsm[lane * 257 + k] = xb[(size_t)k * HW_ + lane];
    }
    __syncthreads();

    // ---- 2. exact argmin (8 threads per pixel) ----
    int p   = t >> 3;
    int pix = pix_base + p;
    int sl  = t & 7;
    int cnt = g_ccnt[pix];
    const float* xr = &xsm[p * 257];
    float a = g_a[pix];
    float bd = 3.4e38f;
    int   bj = 1 << 30;

    if (cnt <= CANDCAP) {
        float thr = g_minh[pix];
        for (int s = sl; s < cnt; s += 8) {
            size_t o = (size_t)pix * CANDCAP + s;
            float h = g_candh[o];
            if (h > thr) continue;                 // final-min filter
            int j = g_candj[o];
            const float4* wr = reinterpret_cast<const float4*>(wt + (size_t)j * C_);
            float dot = 0.f;
            #pragma unroll 8
            for (int q = 0; q < 64; q++) {
                float4 wv = wr[q];
                dot = fmaf(xr[4 * q + 0], wv.x, dot);
                dot = fmaf(xr[4 * q + 1], wv.y, dot);
                dot = fmaf(xr[4 * q + 2], wv.z, dot);
                dot = fmaf(xr[4 * q + 3], wv.w, dot);
            }
            float d2 = __fadd_rn(fmaf(-2.f, dot, a), g_c[j]);
            if (d2 < bd || (d2 == bd && j < bj)) { bd = d2; bj = j; }
        }
    } else {  // safety net: exact full scan (raw overflow, ~never)
        for (int j = sl; j < NCODE; j += 8) {
            const float4* wr = reinterpret_cast<const float4*>(wt + (size_t)j * C_);
            float dot = 0.f;
            #pragma unroll 8
            for (int q = 0; q < 64; q++) {
                float4 wv = wr[q];
                dot = fmaf(xr[4 * q + 0], wv.x, dot);
                dot = fmaf(xr[4 * q + 1], wv.y, dot);
                dot = fmaf(xr[4 * q + 2], wv.z, dot);
                dot = fmaf(xr[4 * q + 3], wv.w, dot);
            }
            float d2 = __fadd_rn(fmaf(-2.f, dot, a), g_c[j]);
            if (d2 < bd || (d2 == bd && j < bj)) { bd = d2; bj = j; }
        }
    }
    sd[t] = bd; sj[t] = bj;
    __syncthreads();
    if (sl == 0) {
        #pragma unroll
        for (int k = 1; k < 8; k++) {
            float d = sd[t + k]; int j = sj[t + k];
            if (d < bd || (d == bd && j < bj)) { bd = d; bj = j; }
        }
        lidx[p] = bj;
        if (write_idx) out_idx[pix] = (float)bj;
    }
    __syncthreads();

    // ---- 3. gather 32 chosen rows transposed: wsm[ci][r] ----
    for (int rit = 0; rit < 4; rit++) {
        int r = warp + 8 * rit;
        const float* row = wt + (size_t)lidx[r] * C_;
        #pragma unroll
        for (int kit = 0; kit < 8; kit++) {
            int ci = lane + 32 * kit;
            wsm[ci * 33 + r] = row[ci];
        }
    }
    __syncthreads();

    // ---- 4. write q + ste (x from smem; 128B coalesced stores) ----
    for (int cit = 0; cit < 32; cit++) {
        int ci = warp + 8 * cit;
        size_t o = (size_t)b * C_ * HW_ + (size_t)ci * HW_ + hw0 + lane;
        float q = wsm[ci * 33 + lane];
        out_q[o] = q;
        if (has_ste) {
            float xv = xsm[lane * 257 + ci];
            out_ste[o] = __fadd_rn(__fsub_rn(q, xv), xv);
        }
    }
}

// ---------------------------------------------------------------------------
extern "C" void kernel_launch(void* const* d_in, const int* in_sizes, int n_in,
                              void* d_out, int out_size) {
    const float* x  = (const float*)d_in[0];
    const float* wt = (const float*)d_in[1];
    float* out = (float*)d_out;

    const long long qsz = (long long)NPIX * C_;
    int has_ste = (out_size >= (int)(2 * qsz)) ? 1 : 0;
    int has_idx = (out_size >= (int)(2 * qsz) + NPIX) ||
                  (out_size == (int)qsz + NPIX);
    float* out_q   = out;
    float* out_ste = out + qsz;
    float* out_idx = has_ste ? out + 2 * qsz : out + qsz;

    const int s3_smem = (32 * 257 + 256 * 33) * 4;   // 66688 bytes

    cudaFuncSetAttribute(t_bf_kernel,
        cudaFuncAttributeMaxDynamicSharedMemorySize, 256 * 132 * 4);
    cudaFuncSetAttribute(g_kernel,
        cudaFuncAttributeMaxDynamicSharedMemorySize, 98304);
    cudaFuncSetAttribute(s3_kernel,
        cudaFuncAttributeMaxDynamicSharedMemorySize, s3_smem);

    c_kernel<<<4, 256>>>(wt);
    wcvt_kernel<<<NCODE * C_ / 2 / 256, 256>>>(wt);
    t_bf_kernel<<<NPIX / 128, 512, 256 * 132 * 4>>>(x);
    g_kernel<<<NPIX / 128, 256, 98304>>>();
    s3_kernel<<<NPIX / 32, 256, s3_smem>>>(x, wt, out_q, out_ste, out_idx,
                                           has_idx ? 1 : 0, has_ste);
}